// round 11
// baseline (speedup 1.0000x reference)
#include <cuda_runtime.h>

#define N_NODES 100000
#define N_EDGES 1600000
#define NODE_DIM 128
#define EDGE_DIM 48
#define IN_DIM 176
#define HID 64
#define LN_EPS 1e-5f
#define N_PAD 100352
#define XP 132
#define N_TILES 782          /* ceil(100000/128) */
#define FUSED_BLOCKS 296     /* 2 per SM x 148 SMs */
#define CAP 64               /* bucket slots per node */
#define OVF_CAP (1 << 20)

// ---------------- scratch (static device globals, zero-initialized) --------
__device__ int   g_cnt[N_NODES];              // per-node edge count (self-resetting)
__device__ int   g_bkt[(size_t)N_NODES * CAP];
__device__ int2  g_ovf[OVF_CAP];
__device__ int   g_ovfCnt;                    // reset by last k_fused block
__device__ int   g_ticket;                    // reset by last k_fused block
__device__ int   g_done;
__device__ float g_pre[(size_t)N_PAD * HID];

typedef unsigned long long ull;

// ---------------- packed f32x2 helpers -------------------------------------
__device__ __forceinline__ ull ffma2(ull a, ull b, ull c) {
    ull d;
    asm("fma.rn.f32x2 %0, %1, %2, %3;" : "=l"(d) : "l"(a), "l"(b), "l"(c));
    return d;
}
__device__ __forceinline__ ull fadd2(ull a, ull b) {
    ull d;
    asm("add.rn.f32x2 %0, %1, %2;" : "=l"(d) : "l"(a), "l"(b));
    return d;
}
__device__ __forceinline__ ull fmul2(ull a, ull b) {
    ull d;
    asm("mul.rn.f32x2 %0, %1, %2;" : "=l"(d) : "l"(a), "l"(b));
    return d;
}
__device__ __forceinline__ ull dup2(float x) {
    ull d; unsigned u = __float_as_uint(x);
    asm("mov.b64 %0, {%1, %1};" : "=l"(d) : "r"(u));
    return d;
}
__device__ __forceinline__ ull pack2(float lo, float hi) {
    ull d;
    asm("mov.b64 %0, {%1, %2};" : "=l"(d)
        : "r"(__float_as_uint(lo)), "r"(__float_as_uint(hi)));
    return d;
}
__device__ __forceinline__ void unpack2(ull a, float& lo, float& hi) {
    unsigned l, h;
    asm("mov.b64 {%0, %1}, %2;" : "=r"(l), "=r"(h) : "l"(a));
    lo = __uint_as_float(l);
    hi = __uint_as_float(h);
}

// ---------------- single-pass bucket build ---------------------------------
__device__ __forceinline__ void bucket_put(int node, int e) {
    int c = atomicAdd(&g_cnt[node], 1);
    if (c < CAP) {
        g_bkt[(size_t)node * CAP + c] = e;
    } else {
        int o = atomicAdd(&g_ovfCnt, 1);
        if (o < OVF_CAP) g_ovf[o] = make_int2(node, e);
    }
}

__global__ void k_bucket(const int4* __restrict__ recv4) {
    int i = blockIdx.x * blockDim.x + threadIdx.x;
    if (i < N_EDGES / 4) {
        int4 r = recv4[i];
        int e0 = i * 4;
        bucket_put(r.x, e0);
        bucket_put(r.y, e0 + 1);
        bucket_put(r.z, e0 + 2);
        bucket_put(r.w, e0 + 3);
    }
}

// ---------------- MLP core pieces ------------------------------------------
// k_fused variant: 256 threads, acc[4][4], 8 nodes per thread
template<int K>
__device__ __forceinline__ void gemm_acc(const float* __restrict__ sIn,
                                         const float* __restrict__ sW,
                                         int j0, int nb, ull acc[4][4]) {
    #pragma unroll 8
    for (int k = 0; k < K; k++) {
        const ulonglong2* xp = (const ulonglong2*)(sIn + k * XP + nb);
        ulonglong2 xa = xp[0];
        ulonglong2 xb = xp[1];
        float4 w = *(const float4*)(sW + k * HID + j0);
        ull w0 = dup2(w.x), w1 = dup2(w.y), w2 = dup2(w.z), w3 = dup2(w.w);
        acc[0][0] = ffma2(xa.x, w0, acc[0][0]);
        acc[0][1] = ffma2(xa.x, w1, acc[0][1]);
        acc[0][2] = ffma2(xa.x, w2, acc[0][2]);
        acc[0][3] = ffma2(xa.x, w3, acc[0][3]);
        acc[1][0] = ffma2(xa.y, w0, acc[1][0]);
        acc[1][1] = ffma2(xa.y, w1, acc[1][1]);
        acc[1][2] = ffma2(xa.y, w2, acc[1][2]);
        acc[1][3] = ffma2(xa.y, w3, acc[1][3]);
        acc[2][0] = ffma2(xb.x, w0, acc[2][0]);
        acc[2][1] = ffma2(xb.x, w1, acc[2][1]);
        acc[2][2] = ffma2(xb.x, w2, acc[2][2]);
        acc[2][3] = ffma2(xb.x, w3, acc[2][3]);
        acc[3][0] = ffma2(xb.y, w0, acc[3][0]);
        acc[3][1] = ffma2(xb.y, w1, acc[3][1]);
        acc[3][2] = ffma2(xb.y, w2, acc[3][2]);
        acc[3][3] = ffma2(xb.y, w3, acc[3][3]);
    }
}

// k_mlp1 variant: 512 threads, acc[2][4], 4 nodes per thread
template<int K>
__device__ __forceinline__ void gemm_half(const float* __restrict__ sIn,
                                          const float* __restrict__ sW,
                                          int j0, int nb, ull acc[2][4]) {
    #pragma unroll 8
    for (int k = 0; k < K; k++) {
        ulonglong2 xa = *(const ulonglong2*)(sIn + k * XP + nb);
        float4 w = *(const float4*)(sW + k * HID + j0);
        ull w0 = dup2(w.x), w1 = dup2(w.y), w2 = dup2(w.z), w3 = dup2(w.w);
        acc[0][0] = ffma2(xa.x, w0, acc[0][0]);
        acc[0][1] = ffma2(xa.x, w1, acc[0][1]);
        acc[0][2] = ffma2(xa.x, w2, acc[0][2]);
        acc[0][3] = ffma2(xa.x, w3, acc[0][3]);
        acc[1][0] = ffma2(xa.y, w0, acc[1][0]);
        acc[1][1] = ffma2(xa.y, w1, acc[1][1]);
        acc[1][2] = ffma2(xa.y, w2, acc[1][2]);
        acc[1][3] = ffma2(xa.y, w3, acc[1][3]);
    }
}

__device__ __forceinline__ void init_bias(const float* __restrict__ sB,
                                          int j0, ull acc[4][4]) {
    ull bd[4];
    #pragma unroll
    for (int c = 0; c < 4; c++) bd[c] = dup2(sB[j0 + c]);
    #pragma unroll
    for (int p = 0; p < 4; p++)
        #pragma unroll
        for (int c = 0; c < 4; c++) acc[p][c] = bd[c];
}

// ---- branch B: pre1 = nf @ W1[0:128] + b1 (512 thr, 2 blocks/SM) ----------
#define SM1_FLOATS (128 * XP + NODE_DIM * HID + HID)

__global__ void __launch_bounds__(512, 2)
k_mlp1(const float* __restrict__ nf, const float* __restrict__ W1,
       const float* __restrict__ b1) {
    extern __shared__ float sm[];
    float* sXT = sm;
    float* sW  = sm + 128 * XP;
    float* sB  = sW + NODE_DIM * HID;
    int tid = threadIdx.x;
    int n0 = blockIdx.x * 128;

    for (int i = tid; i < NODE_DIM * HID; i += 512) sW[i] = W1[i];
    if (tid < HID) sB[tid] = b1[tid];
    for (int i = tid; i < 128 * NODE_DIM; i += 512) {
        int n = i >> 7, k = i & 127;
        int gn = n0 + n;
        sXT[k * XP + n] = (gn < N_NODES) ? __ldcs(&nf[(size_t)gn * NODE_DIM + k]) : 0.f;
    }
    __syncthreads();

    int cg = tid & 15, ng = tid >> 4;       // 16 col-groups x 32 node-groups
    int j0 = cg * 4, nb = ng * 4;           // 4 cols, 4 nodes (2 pairs)
    ull acc[2][4];
    {
        ull bd[4];
        #pragma unroll
        for (int c = 0; c < 4; c++) bd[c] = dup2(sB[j0 + c]);
        #pragma unroll
        for (int p = 0; p < 2; p++)
            #pragma unroll
            for (int c = 0; c < 4; c++) acc[p][c] = bd[c];
    }
    gemm_half<NODE_DIM>(sXT, sW, j0, nb, acc);

    #pragma unroll
    for (int p = 0; p < 2; p++) {
        float l0, h0, l1, h1, l2, h2, l3, h3;
        unpack2(acc[p][0], l0, h0); unpack2(acc[p][1], l1, h1);
        unpack2(acc[p][2], l2, h2); unpack2(acc[p][3], l3, h3);
        int nA = n0 + nb + 2 * p;
        float4 oA = make_float4(l0, l1, l2, l3);
        float4 oB = make_float4(h0, h1, h2, h3);
        *(float4*)(g_pre + (size_t)nA * HID + j0) = oA;
        *(float4*)(g_pre + (size_t)(nA + 1) * HID + j0) = oB;
    }
}

// ---- persistent fused join: bucket gather + 128-node-tile MLP + LN --------
#define SM2_FLOATS (HID * XP + EDGE_DIM * HID + 2 * HID * HID + 4 * HID)

__global__ void __launch_bounds__(256, 2)
k_fused(const float* __restrict__ ef,
        const float* __restrict__ W1,
        const float* __restrict__ W2, const float* __restrict__ b2,
        const float* __restrict__ W3, const float* __restrict__ b3,
        const float* __restrict__ gamma, const float* __restrict__ beta,
        float* __restrict__ out) {
    extern __shared__ float sm[];
    float* sA   = sm;                       // 64 x XP; rows 0..47 = agg means
    float* sW1b = sm + HID * XP;
    float* sW2  = sW1b + EDGE_DIM * HID;
    float* sW3  = sW2 + HID * HID;
    float* sV   = sW3 + HID * HID;
    __shared__ int sTile;
    int tid = threadIdx.x;

    // stage weights ONCE per persistent block
    for (int i = tid; i < EDGE_DIM * HID; i += 256) sW1b[i] = W1[NODE_DIM * HID + i];
    for (int i = tid; i < HID * HID; i += 256) { sW2[i] = W2[i]; sW3[i] = W3[i]; }
    if (tid < HID) {
        sV[tid]           = b2[tid];
        sV[HID + tid]     = b3[tid];
        sV[2 * HID + tid] = gamma[tid];
        sV[3 * HID + tid] = beta[tid];
    }

    int nlg = tid >> 2, sub = tid & 3;      // gather: 4 lanes per node
    int cg = tid & 15, ng = tid >> 4;       // GEMM mapping
    int j0 = cg * 4, nb = ng * 8;
    const float4* ef4 = (const float4*)ef;

    for (;;) {
        __syncthreads();                    // sA free from previous tile
        if (tid == 0) sTile = atomicAdd(&g_ticket, 1);
        __syncthreads();
        int tile = sTile;
        if (tile >= N_TILES) break;
        int n0 = tile * 128;

        // ---- gather-mean from buckets (per-thread prefetch chain) ---------
        #pragma unroll 1
        for (int pass = 0; pass < 2; pass++) {
            int nl = pass * 64 + nlg;
            int gn = n0 + nl;
            float4 a0 = make_float4(0.f, 0.f, 0.f, 0.f), a1 = a0, a2 = a0;
            int d = 0;
            if (gn < N_NODES) {
                d = __ldg(&g_cnt[gn]);
                int nbk = d < CAP ? d : CAP;
                const int* bkt = g_bkt + (size_t)gn * CAP;
                int p = 0;
                int eid = (p < nbk) ? __ldg(&bkt[0]) : 0;
                while (p < nbk) {
                    int nxt = (p + 1 < nbk) ? __ldg(&bkt[p + 1]) : 0;
                    const float4* row = ef4 + (size_t)eid * 12 + sub * 3;
                    float4 r0 = __ldcs(row), r1 = __ldcs(row + 1), r2 = __ldcs(row + 2);
                    a0.x += r0.x; a0.y += r0.y; a0.z += r0.z; a0.w += r0.w;
                    a1.x += r1.x; a1.y += r1.y; a1.z += r1.z; a1.w += r1.w;
                    a2.x += r2.x; a2.y += r2.y; a2.z += r2.z; a2.w += r2.w;
                    eid = nxt;
                    p++;
                }
                if (d > CAP) {              // correctness fallback (never hot)
                    int m = g_ovfCnt;
                    if (m > OVF_CAP) m = OVF_CAP;
                    for (int o = 0; o < m; o++) {
                        int2 en = g_ovf[o];
                        if (en.x == gn) {
                            const float4* row = ef4 + (size_t)en.y * 12 + sub * 3;
                            float4 r0 = row[0], r1 = row[1], r2 = row[2];
                            a0.x += r0.x; a0.y += r0.y; a0.z += r0.z; a0.w += r0.w;
                            a1.x += r1.x; a1.y += r1.y; a1.z += r1.z; a1.w += r1.w;
                            a2.x += r2.x; a2.y += r2.y; a2.z += r2.z; a2.w += r2.w;
                        }
                    }
                }
                if (sub == 0) g_cnt[gn] = 0;   // self-reset for next replay
            }
            float sc = 1.0f / (float)(d > 0 ? d : 1);
            float* col = sA + nl;
            int r0b = sub * 12;
            col[(r0b + 0) * XP] = a0.x * sc;  col[(r0b + 1) * XP] = a0.y * sc;
            col[(r0b + 2) * XP] = a0.z * sc;  col[(r0b + 3) * XP] = a0.w * sc;
            col[(r0b + 4) * XP] = a1.x * sc;  col[(r0b + 5) * XP] = a1.y * sc;
            col[(r0b + 6) * XP] = a1.z * sc;  col[(r0b + 7) * XP] = a1.w * sc;
            col[(r0b + 8) * XP] = a2.x * sc;  col[(r0b + 9) * XP] = a2.y * sc;
            col[(r0b + 10) * XP] = a2.z * sc; col[(r0b + 11) * XP] = a2.w * sc;
        }

        ull acc[4][4];
        // init acc from pre1 (nf @ W1a + b1), coalesced
        #pragma unroll
        for (int p = 0; p < 4; p++) {
            int nA = n0 + nb + 2 * p;
            float4 qa = *(const float4*)(g_pre + (size_t)nA * HID + j0);
            float4 qb = *(const float4*)(g_pre + (size_t)(nA + 1) * HID + j0);
            acc[p][0] = pack2(qa.x, qb.x);
            acc[p][1] = pack2(qa.y, qb.y);
            acc[p][2] = pack2(qa.z, qb.z);
            acc[p][3] = pack2(qa.w, qb.w);
        }
        __syncthreads();

        // layer 1 (agg part) + relu -> sA
        gemm_acc<EDGE_DIM>(sA, sW1b, j0, nb, acc);
        __syncthreads();
        #pragma unroll
        for (int p = 0; p < 4; p++)
            #pragma unroll
            for (int c = 0; c < 4; c++) {
                float lo, hi; unpack2(acc[p][c], lo, hi);
                *(ull*)(sA + (j0 + c) * XP + nb + 2 * p) =
                    pack2(fmaxf(lo, 0.f), fmaxf(hi, 0.f));
            }
        __syncthreads();

        // layer 2 + relu -> sA
        init_bias(sV, j0, acc);
        gemm_acc<HID>(sA, sW2, j0, nb, acc);
        __syncthreads();
        #pragma unroll
        for (int p = 0; p < 4; p++)
            #pragma unroll
            for (int c = 0; c < 4; c++) {
                float lo, hi; unpack2(acc[p][c], lo, hi);
                *(ull*)(sA + (j0 + c) * XP + nb + 2 * p) =
                    pack2(fmaxf(lo, 0.f), fmaxf(hi, 0.f));
            }
        __syncthreads();

        // layer 3 + LayerNorm
        init_bias(sV + HID, j0, acc);
        gemm_acc<HID>(sA, sW3, j0, nb, acc);

        float gm[4], bt[4];
        #pragma unroll
        for (int c = 0; c < 4; c++) {
            gm[c] = sV[2 * HID + j0 + c];
            bt[c] = sV[3 * HID + j0 + c];
        }

        #pragma unroll
        for (int p = 0; p < 4; p++) {
            ull s = fadd2(fadd2(acc[p][0], acc[p][1]), fadd2(acc[p][2], acc[p][3]));
            #pragma unroll
            for (int m = 1; m < 16; m <<= 1)
                s = fadd2(s, __shfl_xor_sync(0xffffffffu, s, m));
            ull nmean = fmul2(s, dup2(-1.0f / 64.0f));
            ull d0 = fadd2(acc[p][0], nmean);
            ull d1 = fadd2(acc[p][1], nmean);
            ull d2 = fadd2(acc[p][2], nmean);
            ull d3 = fadd2(acc[p][3], nmean);
            ull q = fmul2(d0, d0);
            q = ffma2(d1, d1, q);
            q = ffma2(d2, d2, q);
            q = ffma2(d3, d3, q);
            #pragma unroll
            for (int m = 1; m < 16; m <<= 1)
                q = fadd2(q, __shfl_xor_sync(0xffffffffu, q, m));
            ull var = fmul2(q, dup2(1.0f / 64.0f));
            float vlo, vhi; unpack2(var, vlo, vhi);
            float rlo = rsqrtf(vlo + LN_EPS);
            float rhi = rsqrtf(vhi + LN_EPS);
            float l0, h0, l1, h1, l2, h2, l3, h3;
            unpack2(d0, l0, h0); unpack2(d1, l1, h1);
            unpack2(d2, l2, h2); unpack2(d3, l3, h3);
            int nA = n0 + nb + 2 * p, nB = nA + 1;
            if (nA < N_NODES) {
                float4 o;
                o.x = l0 * rlo * gm[0] + bt[0];
                o.y = l1 * rlo * gm[1] + bt[1];
                o.z = l2 * rlo * gm[2] + bt[2];
                o.w = l3 * rlo * gm[3] + bt[3];
                *(float4*)(out + (size_t)nA * HID + j0) = o;
            }
            if (nB < N_NODES) {
                float4 o;
                o.x = h0 * rhi * gm[0] + bt[0];
                o.y = h1 * rhi * gm[1] + bt[1];
                o.z = h2 * rhi * gm[2] + bt[2];
                o.w = h3 * rhi * gm[3] + bt[3];
                *(float4*)(out + (size_t)nB * HID + j0) = o;
            }
        }
    }

    // restore tickets/overflow for next graph replay (last block out resets)
    if (tid == 0) {
        int prev = atomicAdd(&g_done, 1);
        if (prev == FUSED_BLOCKS - 1) {
            g_done = 0;
            g_ovfCnt = 0;
            __threadfence();
            g_ticket = 0;
        }
    }
}

// ---------------- launch: forked graph (all branches joined) ---------------
extern "C" void kernel_launch(void* const* d_in, const int* in_sizes, int n_in,
                              void* d_out, int out_size) {
    const float* nf = 0;
    const float* ef = 0;
    const float* W1 = 0;
    const int* recv = 0;
    const float* mats[2] = {0, 0};
    const float* vecs[5] = {0, 0, 0, 0, 0};
    int mi = 0, vi = 0;
    for (int i = 0; i < n_in; i++) {
        int s = in_sizes[i];
        const void* p = d_in[i];
        if (s == N_NODES * NODE_DIM) nf = (const float*)p;
        else if (s == N_EDGES * EDGE_DIM) ef = (const float*)p;
        else if (s == N_EDGES) recv = (const int*)p;
        else if (s == IN_DIM * HID) W1 = (const float*)p;
        else if (s == HID * HID) { if (mi < 2) mats[mi++] = (const float*)p; }
        else if (s == HID) { if (vi < 5) vecs[vi++] = (const float*)p; }
    }
    float* out = (float*)d_out;

    cudaFuncSetAttribute(k_mlp1, cudaFuncAttributeMaxDynamicSharedMemorySize,
                         SM1_FLOATS * (int)sizeof(float));
    cudaFuncSetAttribute(k_fused, cudaFuncAttributeMaxDynamicSharedMemorySize,
                         SM2_FLOATS * (int)sizeof(float));

    cudaStream_t s2;
    cudaStreamCreateWithFlags(&s2, cudaStreamNonBlocking);
    cudaEvent_t evF, evB;
    cudaEventCreateWithFlags(&evF, cudaEventDisableTiming);
    cudaEventCreateWithFlags(&evB, cudaEventDisableTiming);

    // fork: branch B (node-feature GEMM) on s2
    cudaEventRecord(evF, 0);
    cudaStreamWaitEvent(s2, evF, 0);
    k_mlp1<<<(N_NODES + 127) / 128, 512, SM1_FLOATS * (int)sizeof(float), s2>>>(
        nf, W1, vecs[0]);
    cudaEventRecord(evB, s2);

    // branch A: single-pass bucket build on default stream
    k_bucket<<<(N_EDGES / 4 + 255) / 256, 256>>>((const int4*)recv);

    // join s2 into stream 0, then persistent fused kernel
    cudaStreamWaitEvent(0, evB, 0);
    k_fused<<<FUSED_BLOCKS, 256, SM2_FLOATS * (int)sizeof(float)>>>(
        ef, W1, mats[0], vecs[1], mats[1], vecs[2], vecs[3], vecs[4], out);
}

// round 12
// speedup vs baseline: 1.0319x; 1.0319x over previous
#include <cuda_runtime.h>

#define N_NODES 100000
#define N_EDGES 1600000
#define NODE_DIM 128
#define EDGE_DIM 48
#define IN_DIM 176
#define HID 64
#define LN_EPS 1e-5f
#define N_PAD 100352
#define XP 132
#define N_TILES 782          /* ceil(100000/128) */
#define FUSED_BLOCKS 296     /* 2 per SM x 148 SMs */
#define CAP 64               /* bucket slots per node */
#define OVF_CAP (1 << 20)

// ---------------- scratch (static device globals, zero-initialized) --------
__device__ int   g_cnt[N_NODES];              // per-node edge count (self-resetting)
__device__ int   g_bkt[(size_t)N_NODES * CAP];
__device__ int2  g_ovf[OVF_CAP];
__device__ int   g_ovfCnt;                    // reset by last k_fused block
__device__ int   g_ticket;                    // reset by last k_fused block
__device__ int   g_done;
__device__ float g_pre[(size_t)N_PAD * HID];

typedef unsigned long long ull;

// ---------------- packed f32x2 helpers -------------------------------------
__device__ __forceinline__ ull ffma2(ull a, ull b, ull c) {
    ull d;
    asm("fma.rn.f32x2 %0, %1, %2, %3;" : "=l"(d) : "l"(a), "l"(b), "l"(c));
    return d;
}
__device__ __forceinline__ ull fadd2(ull a, ull b) {
    ull d;
    asm("add.rn.f32x2 %0, %1, %2;" : "=l"(d) : "l"(a), "l"(b));
    return d;
}
__device__ __forceinline__ ull fmul2(ull a, ull b) {
    ull d;
    asm("mul.rn.f32x2 %0, %1, %2;" : "=l"(d) : "l"(a), "l"(b));
    return d;
}
__device__ __forceinline__ ull dup2(float x) {
    ull d; unsigned u = __float_as_uint(x);
    asm("mov.b64 %0, {%1, %1};" : "=l"(d) : "r"(u));
    return d;
}
__device__ __forceinline__ ull pack2(float lo, float hi) {
    ull d;
    asm("mov.b64 %0, {%1, %2};" : "=l"(d)
        : "r"(__float_as_uint(lo)), "r"(__float_as_uint(hi)));
    return d;
}
__device__ __forceinline__ void unpack2(ull a, float& lo, float& hi) {
    unsigned l, h;
    asm("mov.b64 {%0, %1}, %2;" : "=r"(l), "=r"(h) : "l"(a));
    lo = __uint_as_float(l);
    hi = __uint_as_float(h);
}

// ---------------- single-pass bucket build ---------------------------------
__device__ __forceinline__ void bucket_put(int node, int e) {
    int c = atomicAdd(&g_cnt[node], 1);
    if (c < CAP) {
        g_bkt[(size_t)node * CAP + c] = e;
    } else {
        int o = atomicAdd(&g_ovfCnt, 1);
        if (o < OVF_CAP) g_ovf[o] = make_int2(node, e);
    }
}

__global__ void k_bucket(const int4* __restrict__ recv4) {
    int i = blockIdx.x * blockDim.x + threadIdx.x;
    if (i < N_EDGES / 4) {
        int4 r = recv4[i];
        int e0 = i * 4;
        bucket_put(r.x, e0);
        bucket_put(r.y, e0 + 1);
        bucket_put(r.z, e0 + 2);
        bucket_put(r.w, e0 + 3);
    }
}

// ---------------- MLP core pieces (256 thr, acc[4][4]) ---------------------
template<int K>
__device__ __forceinline__ void gemm_acc(const float* __restrict__ sIn,
                                         const float* __restrict__ sW,
                                         int j0, int nb, ull acc[4][4]) {
    #pragma unroll 8
    for (int k = 0; k < K; k++) {
        const ulonglong2* xp = (const ulonglong2*)(sIn + k * XP + nb);
        ulonglong2 xa = xp[0];
        ulonglong2 xb = xp[1];
        float4 w = *(const float4*)(sW + k * HID + j0);
        ull w0 = dup2(w.x), w1 = dup2(w.y), w2 = dup2(w.z), w3 = dup2(w.w);
        acc[0][0] = ffma2(xa.x, w0, acc[0][0]);
        acc[0][1] = ffma2(xa.x, w1, acc[0][1]);
        acc[0][2] = ffma2(xa.x, w2, acc[0][2]);
        acc[0][3] = ffma2(xa.x, w3, acc[0][3]);
        acc[1][0] = ffma2(xa.y, w0, acc[1][0]);
        acc[1][1] = ffma2(xa.y, w1, acc[1][1]);
        acc[1][2] = ffma2(xa.y, w2, acc[1][2]);
        acc[1][3] = ffma2(xa.y, w3, acc[1][3]);
        acc[2][0] = ffma2(xb.x, w0, acc[2][0]);
        acc[2][1] = ffma2(xb.x, w1, acc[2][1]);
        acc[2][2] = ffma2(xb.x, w2, acc[2][2]);
        acc[2][3] = ffma2(xb.x, w3, acc[2][3]);
        acc[3][0] = ffma2(xb.y, w0, acc[3][0]);
        acc[3][1] = ffma2(xb.y, w1, acc[3][1]);
        acc[3][2] = ffma2(xb.y, w2, acc[3][2]);
        acc[3][3] = ffma2(xb.y, w3, acc[3][3]);
    }
}

__device__ __forceinline__ void init_bias(const float* __restrict__ sB,
                                          int j0, ull acc[4][4]) {
    ull bd[4];
    #pragma unroll
    for (int c = 0; c < 4; c++) bd[c] = dup2(sB[j0 + c]);
    #pragma unroll
    for (int p = 0; p < 4; p++)
        #pragma unroll
        for (int c = 0; c < 4; c++) acc[p][c] = bd[c];
}

// ---- branch B: pre1 = nf @ W1[0:128] + b1 (R10 shape: 256 thr) ------------
#define SM1_FLOATS (128 * XP + NODE_DIM * HID + HID)

__global__ void __launch_bounds__(256)
k_mlp1(const float* __restrict__ nf, const float* __restrict__ W1,
       const float* __restrict__ b1) {
    extern __shared__ float sm[];
    float* sXT = sm;
    float* sW  = sm + 128 * XP;
    float* sB  = sW + NODE_DIM * HID;
    int tid = threadIdx.x;
    int n0 = blockIdx.x * 128;

    for (int i = tid; i < NODE_DIM * HID; i += 256) sW[i] = W1[i];
    if (tid < HID) sB[tid] = b1[tid];
    for (int i = tid; i < 128 * NODE_DIM; i += 256) {
        int n = i >> 7, k = i & 127;
        int gn = n0 + n;
        sXT[k * XP + n] = (gn < N_NODES) ? __ldcs(&nf[(size_t)gn * NODE_DIM + k]) : 0.f;
    }
    __syncthreads();

    int cg = tid & 15, ng = tid >> 4;
    int j0 = cg * 4, nb = ng * 8;
    ull acc[4][4];
    init_bias(sB, j0, acc);
    gemm_acc<NODE_DIM>(sXT, sW, j0, nb, acc);

    #pragma unroll
    for (int p = 0; p < 4; p++) {
        float l0, h0, l1, h1, l2, h2, l3, h3;
        unpack2(acc[p][0], l0, h0); unpack2(acc[p][1], l1, h1);
        unpack2(acc[p][2], l2, h2); unpack2(acc[p][3], l3, h3);
        int nA = n0 + nb + 2 * p;
        float4 oA = make_float4(l0, l1, l2, l3);
        float4 oB = make_float4(h0, h1, h2, h3);
        *(float4*)(g_pre + (size_t)nA * HID + j0) = oA;
        *(float4*)(g_pre + (size_t)(nA + 1) * HID + j0) = oB;
    }
}

// ---- persistent fused join: batched gather + 128-node-tile MLP + LN -------
#define SM2_FLOATS (HID * XP + EDGE_DIM * HID + 2 * HID * HID + 4 * HID)

__device__ __forceinline__ void acc_row(const float4* __restrict__ ef4,
                                        int eid, int sub,
                                        float4& a0, float4& a1, float4& a2) {
    const float4* row = ef4 + (size_t)eid * 12 + sub * 3;
    float4 r0 = __ldcs(row), r1 = __ldcs(row + 1), r2 = __ldcs(row + 2);
    a0.x += r0.x; a0.y += r0.y; a0.z += r0.z; a0.w += r0.w;
    a1.x += r1.x; a1.y += r1.y; a1.z += r1.z; a1.w += r1.w;
    a2.x += r2.x; a2.y += r2.y; a2.z += r2.z; a2.w += r2.w;
}

__global__ void __launch_bounds__(256, 2)
k_fused(const float* __restrict__ ef,
        const float* __restrict__ W1,
        const float* __restrict__ W2, const float* __restrict__ b2,
        const float* __restrict__ W3, const float* __restrict__ b3,
        const float* __restrict__ gamma, const float* __restrict__ beta,
        float* __restrict__ out) {
    extern __shared__ float sm[];
    float* sA   = sm;                       // 64 x XP; rows 0..47 = agg means
    float* sW1b = sm + HID * XP;
    float* sW2  = sW1b + EDGE_DIM * HID;
    float* sW3  = sW2 + HID * HID;
    float* sV   = sW3 + HID * HID;
    __shared__ int sTile;
    int tid = threadIdx.x;

    // stage weights ONCE per persistent block
    for (int i = tid; i < EDGE_DIM * HID; i += 256) sW1b[i] = W1[NODE_DIM * HID + i];
    for (int i = tid; i < HID * HID; i += 256) { sW2[i] = W2[i]; sW3[i] = W3[i]; }
    if (tid < HID) {
        sV[tid]           = b2[tid];
        sV[HID + tid]     = b3[tid];
        sV[2 * HID + tid] = gamma[tid];
        sV[3 * HID + tid] = beta[tid];
    }

    int nlg = tid >> 2, sub = tid & 3;      // gather: 4 lanes per node
    int cg = tid & 15, ng = tid >> 4;       // GEMM mapping
    int j0 = cg * 4, nb = ng * 8;
    const float4* ef4 = (const float4*)ef;

    for (;;) {
        __syncthreads();                    // sA free from previous tile
        if (tid == 0) sTile = atomicAdd(&g_ticket, 1);
        __syncthreads();
        int tile = sTile;
        if (tile >= N_TILES) break;
        int n0 = tile * 128;

        // ---- gather-mean from buckets: int4 index loads, 4-edge batches ---
        #pragma unroll 1
        for (int pass = 0; pass < 2; pass++) {
            int nl = pass * 64 + nlg;
            int gn = n0 + nl;
            float4 a0 = make_float4(0.f, 0.f, 0.f, 0.f), a1 = a0, a2 = a0;
            int d = 0;
            if (gn < N_NODES) {
                d = __ldg(&g_cnt[gn]);
                int nbk = d < CAP ? d : CAP;
                const int* bkt = g_bkt + (size_t)gn * CAP;
                const int4* bkt4 = (const int4*)bkt;
                int p = 0;
                // batched: 4 indices per int4, 12 independent LDG.128 rows
                #pragma unroll 1
                for (; p + 4 <= nbk; p += 4) {
                    int4 e4 = __ldg(&bkt4[p >> 2]);
                    acc_row(ef4, e4.x, sub, a0, a1, a2);
                    acc_row(ef4, e4.y, sub, a0, a1, a2);
                    acc_row(ef4, e4.z, sub, a0, a1, a2);
                    acc_row(ef4, e4.w, sub, a0, a1, a2);
                }
                // remainder (0..3 edges)
                #pragma unroll 1
                for (; p < nbk; p++) {
                    int eid = __ldg(&bkt[p]);
                    acc_row(ef4, eid, sub, a0, a1, a2);
                }
                if (d > CAP) {              // correctness fallback (never hot)
                    int m = g_ovfCnt;
                    if (m > OVF_CAP) m = OVF_CAP;
                    for (int o = 0; o < m; o++) {
                        int2 en = g_ovf[o];
                        if (en.x == gn) acc_row(ef4, en.y, sub, a0, a1, a2);
                    }
                }
                if (sub == 0) g_cnt[gn] = 0;   // self-reset for next replay
            }
            float sc = 1.0f / (float)(d > 0 ? d : 1);
            float* col = sA + nl;
            int r0b = sub * 12;
            col[(r0b + 0) * XP] = a0.x * sc;  col[(r0b + 1) * XP] = a0.y * sc;
            col[(r0b + 2) * XP] = a0.z * sc;  col[(r0b + 3) * XP] = a0.w * sc;
            col[(r0b + 4) * XP] = a1.x * sc;  col[(r0b + 5) * XP] = a1.y * sc;
            col[(r0b + 6) * XP] = a1.z * sc;  col[(r0b + 7) * XP] = a1.w * sc;
            col[(r0b + 8) * XP] = a2.x * sc;  col[(r0b + 9) * XP] = a2.y * sc;
            col[(r0b + 10) * XP] = a2.z * sc; col[(r0b + 11) * XP] = a2.w * sc;
        }

        ull acc[4][4];
        // init acc from pre1 (nf @ W1a + b1), coalesced
        #pragma unroll
        for (int p = 0; p < 4; p++) {
            int nA = n0 + nb + 2 * p;
            float4 qa = *(const float4*)(g_pre + (size_t)nA * HID + j0);
            float4 qb = *(const float4*)(g_pre + (size_t)(nA + 1) * HID + j0);
            acc[p][0] = pack2(qa.x, qb.x);
            acc[p][1] = pack2(qa.y, qb.y);
            acc[p][2] = pack2(qa.z, qb.z);
            acc[p][3] = pack2(qa.w, qb.w);
        }
        __syncthreads();

        // layer 1 (agg part) + relu -> sA
        gemm_acc<EDGE_DIM>(sA, sW1b, j0, nb, acc);
        __syncthreads();
        #pragma unroll
        for (int p = 0; p < 4; p++)
            #pragma unroll
            for (int c = 0; c < 4; c++) {
                float lo, hi; unpack2(acc[p][c], lo, hi);
                *(ull*)(sA + (j0 + c) * XP + nb + 2 * p) =
                    pack2(fmaxf(lo, 0.f), fmaxf(hi, 0.f));
            }
        __syncthreads();

        // layer 2 + relu -> sA
        init_bias(sV, j0, acc);
        gemm_acc<HID>(sA, sW2, j0, nb, acc);
        __syncthreads();
        #pragma unroll
        for (int p = 0; p < 4; p++)
            #pragma unroll
            for (int c = 0; c < 4; c++) {
                float lo, hi; unpack2(acc[p][c], lo, hi);
                *(ull*)(sA + (j0 + c) * XP + nb + 2 * p) =
                    pack2(fmaxf(lo, 0.f), fmaxf(hi, 0.f));
            }
        __syncthreads();

        // layer 3 + LayerNorm
        init_bias(sV + HID, j0, acc);
        gemm_acc<HID>(sA, sW3, j0, nb, acc);

        float gm[4], bt[4];
        #pragma unroll
        for (int c = 0; c < 4; c++) {
            gm[c] = sV[2 * HID + j0 + c];
            bt[c] = sV[3 * HID + j0 + c];
        }

        #pragma unroll
        for (int p = 0; p < 4; p++) {
            ull s = fadd2(fadd2(acc[p][0], acc[p][1]), fadd2(acc[p][2], acc[p][3]));
            #pragma unroll
            for (int m = 1; m < 16; m <<= 1)
                s = fadd2(s, __shfl_xor_sync(0xffffffffu, s, m));
            ull nmean = fmul2(s, dup2(-1.0f / 64.0f));
            ull d0 = fadd2(acc[p][0], nmean);
            ull d1 = fadd2(acc[p][1], nmean);
            ull d2 = fadd2(acc[p][2], nmean);
            ull d3 = fadd2(acc[p][3], nmean);
            ull q = fmul2(d0, d0);
            q = ffma2(d1, d1, q);
            q = ffma2(d2, d2, q);
            q = ffma2(d3, d3, q);
            #pragma unroll
            for (int m = 1; m < 16; m <<= 1)
                q = fadd2(q, __shfl_xor_sync(0xffffffffu, q, m));
            ull var = fmul2(q, dup2(1.0f / 64.0f));
            float vlo, vhi; unpack2(var, vlo, vhi);
            float rlo = rsqrtf(vlo + LN_EPS);
            float rhi = rsqrtf(vhi + LN_EPS);
            float l0, h0, l1, h1, l2, h2, l3, h3;
            unpack2(d0, l0, h0); unpack2(d1, l1, h1);
            unpack2(d2, l2, h2); unpack2(d3, l3, h3);
            int nA = n0 + nb + 2 * p, nB = nA + 1;
            if (nA < N_NODES) {
                float4 o;
                o.x = l0 * rlo * gm[0] + bt[0];
                o.y = l1 * rlo * gm[1] + bt[1];
                o.z = l2 * rlo * gm[2] + bt[2];
                o.w = l3 * rlo * gm[3] + bt[3];
                *(float4*)(out + (size_t)nA * HID + j0) = o;
            }
            if (nB < N_NODES) {
                float4 o;
                o.x = h0 * rhi * gm[0] + bt[0];
                o.y = h1 * rhi * gm[1] + bt[1];
                o.z = h2 * rhi * gm[2] + bt[2];
                o.w = h3 * rhi * gm[3] + bt[3];
                *(float4*)(out + (size_t)nB * HID + j0) = o;
            }
        }
    }

    // restore tickets/overflow for next graph replay (last block out resets)
    if (tid == 0) {
        int prev = atomicAdd(&g_done, 1);
        if (prev == FUSED_BLOCKS - 1) {
            g_done = 0;
            g_ovfCnt = 0;
            __threadfence();
            g_ticket = 0;
        }
    }
}

// ---------------- launch: forked graph (all branches joined) ---------------
extern "C" void kernel_launch(void* const* d_in, const int* in_sizes, int n_in,
                              void* d_out, int out_size) {
    const float* nf = 0;
    const float* ef = 0;
    const float* W1 = 0;
    const int* recv = 0;
    const float* mats[2] = {0, 0};
    const float* vecs[5] = {0, 0, 0, 0, 0};
    int mi = 0, vi = 0;
    for (int i = 0; i < n_in; i++) {
        int s = in_sizes[i];
        const void* p = d_in[i];
        if (s == N_NODES * NODE_DIM) nf = (const float*)p;
        else if (s == N_EDGES * EDGE_DIM) ef = (const float*)p;
        else if (s == N_EDGES) recv = (const int*)p;
        else if (s == IN_DIM * HID) W1 = (const float*)p;
        else if (s == HID * HID) { if (mi < 2) mats[mi++] = (const float*)p; }
        else if (s == HID) { if (vi < 5) vecs[vi++] = (const float*)p; }
    }
    float* out = (float*)d_out;

    cudaFuncSetAttribute(k_mlp1, cudaFuncAttributeMaxDynamicSharedMemorySize,
                         SM1_FLOATS * (int)sizeof(float));
    cudaFuncSetAttribute(k_fused, cudaFuncAttributeMaxDynamicSharedMemorySize,
                         SM2_FLOATS * (int)sizeof(float));

    cudaStream_t s2;
    cudaStreamCreateWithFlags(&s2, cudaStreamNonBlocking);
    cudaEvent_t evF, evB;
    cudaEventCreateWithFlags(&evF, cudaEventDisableTiming);
    cudaEventCreateWithFlags(&evB, cudaEventDisableTiming);

    // fork: branch B (node-feature GEMM) on s2
    cudaEventRecord(evF, 0);
    cudaStreamWaitEvent(s2, evF, 0);
    k_mlp1<<<(N_NODES + 127) / 128, 256, SM1_FLOATS * (int)sizeof(float), s2>>>(
        nf, W1, vecs[0]);
    cudaEventRecord(evB, s2);

    // branch A: single-pass bucket build on default stream
    k_bucket<<<(N_EDGES / 4 + 255) / 256, 256>>>((const int4*)recv);

    // join s2 into stream 0, then persistent fused kernel
    cudaStreamWaitEvent(0, evB, 0);
    k_fused<<<FUSED_BLOCKS, 256, SM2_FLOATS * (int)sizeof(float)>>>(
        ef, W1, mats[0], vecs[1], mats[1], vecs[2], vecs[3], vecs[4], out);
}